// round 7
// baseline (speedup 1.0000x reference)
#include <cuda_runtime.h>
#include <cuda_fp16.h>
#include <cstdint>

#define DI __device__ __forceinline__

namespace {

constexpr int kT = 28;
constexpr int kI = 28;
constexpr int kH = 128;
constexpr int kC = 10;
constexpr int WARPS = 4;
constexpr int THREADS = WARPS * 32;       // 128
constexpr int TILES = 32768 / 32;         // 1024 warp-tiles (m32)
constexpr int GRID = TILES / WARPS;       // 256

// SMEM: paired-B fragment tables (uint4 per lane per (kt, nt-pair))
constexpr unsigned OFF_W = 0;                   // [8kt][8ntp][32][16B] = 32768
constexpr unsigned OFF_U = 32768;               // [2kt][8ntp][32][16B] = 8192
constexpr unsigned OFF_V = 32768 + 8192;        // [8kt][1ntp][32][16B] = 4096
constexpr unsigned SMEM_TOTAL = OFF_V + 4096;   // 45056 -> 2 CTAs/SM

// pack two fp32 -> fp16x2 (lo = a, hi = b)
DI unsigned packh(float a, float b) {
  unsigned d;
  asm("cvt.rn.f16x2.f32 %0, %1, %2;" : "=r"(d) : "f"(b), "f"(a));
  return d;
}
DI unsigned packh2(float2 v) { return packh(v.x, v.y); }

DI unsigned th2(unsigned h2) {  // tanh on fp16x2, one MUFU per 2 elems
  unsigned r;
  asm("tanh.approx.f16x2 %0, %1;" : "=r"(r) : "r"(h2));
  return r;
}

// C += A(m16k16 f16) * B(k16n8 f16), fp32 accumulate
DI void mma16(float* c, const unsigned* a, unsigned bx, unsigned by) {
  asm("mma.sync.aligned.m16n8k16.row.col.f32.f16.f16.f32 "
      "{%0,%1,%2,%3},{%4,%5,%6,%7},{%8,%9},{%0,%1,%2,%3};"
      : "+f"(c[0]), "+f"(c[1]), "+f"(c[2]), "+f"(c[3])
      : "r"(a[0]), "r"(a[1]), "r"(a[2]), "r"(a[3]), "r"(bx), "r"(by));
}
DI void mma16z(float* c, const unsigned* a, unsigned bx, unsigned by) {
  asm("mma.sync.aligned.m16n8k16.row.col.f32.f16.f16.f32 "
      "{%0,%1,%2,%3},{%4,%5,%6,%7},{%8,%9},{%10,%10,%10,%10};"
      : "=f"(c[0]), "=f"(c[1]), "=f"(c[2]), "=f"(c[3])
      : "r"(a[0]), "r"(a[1]), "r"(a[2]), "r"(a[3]), "r"(bx), "r"(by),
        "f"(0.0f));
}

// B element (n,k) -> byte offset; ntpn = nt-pairs per kt (W/U: 8, V: 1)
DI unsigned bpos(int n, int k, int ntpn) {
  int kt = k >> 4, kk = k & 15, nt = n >> 3, rr = n & 7;
  int ntp = nt >> 1, sel = nt & 1;
  int ln = rr * 4 + ((kk >> 1) & 3);
  return (unsigned)((((kt * ntpn + ntp) * 32 + ln) << 4) + sel * 8 +
                    ((kk >> 3) & 1) * 4 + (kk & 1) * 2);
}

__global__ void __launch_bounds__(THREADS, 2) rnn_kernel(
    const float* __restrict__ x, const float* __restrict__ Uw,
    const float* __restrict__ Ub, const float* __restrict__ Ww,
    const float* __restrict__ Wb, const float* __restrict__ Vw,
    const float* __restrict__ Vb, float* __restrict__ out) {
  extern __shared__ __align__(16) char sm[];
  const int tid = threadIdx.x;
  const int w = tid >> 5, lane = tid & 31;
  const int r = lane >> 2, q = lane & 3;

  // ---- fp16 paired-B fragment tables, biases folded into U col 28 ----
  for (int idx = tid; idx < kH * kH; idx += THREADS) {  // W^T[k][n] = Ww[n*128+k]
    int n = idx >> 7, k = idx & 127;
    *(__half*)(sm + OFF_W + bpos(n, k, 8)) = __float2half_rn(Ww[idx]);
  }
  for (int idx = tid; idx < kH * 32; idx += THREADS) {  // U^T padded K=32
    int n = idx >> 5, k = idx & 31;
    float v = (k < kI) ? Uw[n * kI + k] : ((k == kI) ? (Ub[n] + Wb[n]) : 0.0f);
    *(__half*)(sm + OFF_U + bpos(n, k, 8)) = __float2half_rn(v);
  }
  for (int idx = tid; idx < 16 * kH; idx += THREADS) {  // V^T padded N=16
    int n = idx >> 7, k = idx & 127;
    float v = (n < kC) ? Vw[n * kH + k] : 0.0f;
    *(__half*)(sm + OFF_V + bpos(n, k, 1)) = __float2half_rn(v);
  }
  __syncthreads();

  const int g = blockIdx.x * WARPS + w;  // warp-tile of 32 batch rows
  // lane's A-fragment rows per m-tile: g*32 + m*16 + {r, r+8}
  const float* xb[2][2];
#pragma unroll
  for (int m = 0; m < 2; m++) {
    xb[m][0] = x + (long)(g * 32 + m * 16 + r) * (kT * kI);
    xb[m][1] = xb[m][0] + 8 * (kT * kI);
  }

  float2 xraw[2][8];
  auto ldx = [&](int t) {
#pragma unroll
    for (int m = 0; m < 2; m++) {
      const float* p0 = xb[m][0] + t * kI;
      const float* p1 = xb[m][1] + t * kI;
      xraw[m][0] = *(const float2*)(p0 + 2 * q);
      xraw[m][1] = *(const float2*)(p0 + 8 + 2 * q);
      xraw[m][2] = *(const float2*)(p0 + 16 + 2 * q);
      xraw[m][4] = *(const float2*)(p1 + 2 * q);
      xraw[m][5] = *(const float2*)(p1 + 8 + 2 * q);
      xraw[m][6] = *(const float2*)(p1 + 16 + 2 * q);
      if (q < 2) {
        xraw[m][3] = *(const float2*)(p0 + 24 + 2 * q);
        xraw[m][7] = *(const float2*)(p1 + 24 + 2 * q);
      }
    }
  };
  unsigned xf[2][2][4];  // A-fragments of [x_t | 1 | 0pad] per m-tile
  auto cvtx = [&] {
    const unsigned cpad = (q == 2) ? 0x00003C00u : 0u;  // cols 28..31 = 1,0,0,0
#pragma unroll
    for (int m = 0; m < 2; m++) {
      xf[m][0][0] = packh2(xraw[m][0]);
      xf[m][0][1] = packh2(xraw[m][4]);
      xf[m][0][2] = packh2(xraw[m][1]);
      xf[m][0][3] = packh2(xraw[m][5]);
      xf[m][1][0] = packh2(xraw[m][2]);
      xf[m][1][1] = packh2(xraw[m][6]);
      xf[m][1][2] = (q < 2) ? packh2(xraw[m][3]) : cpad;
      xf[m][1][3] = (q < 2) ? packh2(xraw[m][7]) : cpad;
    }
  };

  ldx(0);
  cvtx();

  unsigned A[2][8][4];  // state S fragments (fp16x2) per m-tile
  float C[2][16][4];    // fp32 accumulators

#pragma unroll 1
  for (int t = 0; t < kT; t++) {
    // U part: C = x_t @ U^T (+ biases); first kt initializes C
    {
      const uint4* b0 = (const uint4*)(sm + OFF_U) + lane;
      const uint4* b1 = b0 + 256;
#pragma unroll
      for (int i = 0; i < 8; i++) {
        uint4 bb = b0[i * 32];
#pragma unroll
        for (int m = 0; m < 2; m++) {
          mma16z(C[m][2 * i], xf[m][0], bb.x, bb.y);
          mma16z(C[m][2 * i + 1], xf[m][0], bb.z, bb.w);
        }
      }
#pragma unroll
      for (int i = 0; i < 8; i++) {
        uint4 bb = b1[i * 32];
#pragma unroll
        for (int m = 0; m < 2; m++) {
          mma16(C[m][2 * i], xf[m][1], bb.x, bb.y);
          mma16(C[m][2 * i + 1], xf[m][1], bb.z, bb.w);
        }
      }
    }
    // prefetch x_{t+1} under the W MMAs
    if (t + 1 < kT) ldx(t + 1);
    // W part: C += S_{t-1} @ W^T (one B load feeds 4 MMAs)
    if (t > 0) {
#pragma unroll
      for (int kt = 0; kt < 8; kt++) {
        const uint4* bb = (const uint4*)(sm + OFF_W) + kt * 256 + lane;
#pragma unroll
        for (int i = 0; i < 8; i++) {
          uint4 b = bb[i * 32];
#pragma unroll
          for (int m = 0; m < 2; m++) {
            mma16(C[m][2 * i], A[m][kt], b.x, b.y);
            mma16(C[m][2 * i + 1], A[m][kt], b.z, b.w);
          }
        }
      }
    }
    // transform: pack -> tanh.f16x2 -> A fragments (lane-identical remap)
#pragma unroll
    for (int m = 0; m < 2; m++)
#pragma unroll
      for (int i = 0; i < 8; i++) {
        A[m][i][0] = th2(packh(C[m][2 * i][0], C[m][2 * i][1]));
        A[m][i][1] = th2(packh(C[m][2 * i][2], C[m][2 * i][3]));
        A[m][i][2] = th2(packh(C[m][2 * i + 1][0], C[m][2 * i + 1][1]));
        A[m][i][3] = th2(packh(C[m][2 * i + 1][2], C[m][2 * i + 1][3]));
      }
    if (t + 1 < kT) cvtx();
  }

  // output: out = S @ V^T + V_b (N padded to 16 = one nt-pair, kt stride 32)
  const float vb0 = __ldg(Vb + 2 * q), vb1 = __ldg(Vb + 2 * q + 1);
  const float vb8 = __ldg(Vb + 8), vb9 = __ldg(Vb + 9);
#pragma unroll
  for (int m = 0; m < 2; m++) {
    float o0[4], o1[4];
    const uint4* bb = (const uint4*)(sm + OFF_V) + lane;
    uint4 b = bb[0];
    mma16z(o0, A[m][0], b.x, b.y);
    mma16z(o1, A[m][0], b.z, b.w);
#pragma unroll
    for (int kt = 1; kt < 8; kt++) {
      b = bb[kt * 32];
      mma16(o0, A[m][kt], b.x, b.y);
      mma16(o1, A[m][kt], b.z, b.w);
    }
    const int row0 = g * 32 + m * 16 + r;
    *(float2*)(out + row0 * kC + 2 * q) = make_float2(o0[0] + vb0, o0[1] + vb1);
    *(float2*)(out + (row0 + 8) * kC + 2 * q) =
        make_float2(o0[2] + vb0, o0[3] + vb1);
    if (q == 0) {
      *(float2*)(out + row0 * kC + 8) = make_float2(o1[0] + vb8, o1[1] + vb9);
      *(float2*)(out + (row0 + 8) * kC + 8) =
          make_float2(o1[2] + vb8, o1[3] + vb9);
    }
  }
}

}  // namespace

extern "C" void kernel_launch(void* const* d_in, const int* in_sizes, int n_in,
                              void* d_out, int out_size) {
  (void)in_sizes; (void)n_in; (void)out_size;
  cudaFuncSetAttribute(rnn_kernel, cudaFuncAttributeMaxDynamicSharedMemorySize,
                       SMEM_TOTAL);
  rnn_kernel<<<GRID, THREADS, SMEM_TOTAL>>>(
      (const float*)d_in[0], (const float*)d_in[1], (const float*)d_in[2],
      (const float*)d_in[3], (const float*)d_in[4], (const float*)d_in[5],
      (const float*)d_in[6], (float*)d_out);
}